// round 2
// baseline (speedup 1.0000x reference)
#include <cuda_runtime.h>
#include <math.h>

#define NPTS 4096
#define DIM  512
#define BIGF   1e30f
#define MARKF  1e30f
#define MARK_TH 1e29f

// ---------------- scratch (static device globals; no allocation) ----------------
__device__ float g_dist[2][(size_t)NPTS * NPTS];   // 2 x 64MB distance matrices
__device__ float g_sq[2][NPTS];                    // squared norms
__device__ float g_deaths[2][NPTS];                // MST edge weights (padded to 4096)
__device__ float g_partials[1024];                 // L2-loss per-block partial sums

// ---------------- squared norms: one warp per row ----------------
__global__ void sq_kernel(const float* __restrict__ x1, const float* __restrict__ x2) {
    int w    = (blockIdx.x * blockDim.x + threadIdx.x) >> 5;   // global warp id, 0..8191
    int lane = threadIdx.x & 31;
    int mat  = w >> 12;
    int row  = w & (NPTS - 1);
    const float* x = mat ? x2 : x1;
    const float* p = x + (size_t)row * DIM;
    float s = 0.f;
    for (int c = lane; c < DIM; c += 32) { float v = p[c]; s += v * v; }
    #pragma unroll
    for (int o = 16; o > 0; o >>= 1) s += __shfl_xor_sync(0xffffffffu, s, o);
    if (lane == 0) g_sq[mat][row] = s;
}

// ---------------- representation loss partials (deterministic) ----------------
__global__ void repr_kernel(const float* __restrict__ x1, const float* __restrict__ x2) {
    __shared__ float red[256];
    size_t base = (size_t)blockIdx.x * 2048;
    float s = 0.f;
    for (int i = threadIdx.x; i < 2048; i += 256) {
        float d = x1[base + i] - x2[base + i];
        s += d * d;
    }
    red[threadIdx.x] = s; __syncthreads();
    #pragma unroll
    for (int st = 128; st > 0; st >>= 1) {
        if (threadIdx.x < st) red[threadIdx.x] += red[threadIdx.x + st];
        __syncthreads();
    }
    if (threadIdx.x == 0) g_partials[blockIdx.x] = red[0];
}

// ---------------- distance matrix: symmetric tiled fp32 GEMM ----------------
// grid.x = 528 upper-tri 128x128 tiles, grid.z = matrix index; 256 threads, 8x8/thread
__global__ void __launch_bounds__(256) dist_kernel(const float* __restrict__ x1,
                                                   const float* __restrict__ x2) {
    int mat = blockIdx.z;
    const float* X  = mat ? x2 : x1;
    float* Dst      = g_dist[mat];
    const float* sq = g_sq[mat];

    // decode (bi, bj) with bi <= bj from linear upper-triangle index
    int t = blockIdx.x, bi = 0, len = 32;
    while (t >= len) { t -= len; len--; bi++; }
    int bj = bi + t;

    __shared__ float As[8][128];
    __shared__ float Bs[8][128];
    __shared__ float sqA[128], sqB[128];

    int tid = threadIdx.x;
    if (tid < 128) sqA[tid] = sq[bi * 128 + tid];
    else           sqB[tid - 128] = sq[bj * 128 + (tid - 128)];

    int lr = tid >> 1;            // row within tile (0..127)
    int lc = (tid & 1) * 4;       // 0 or 4 (column-quad within BK=8)
    const float* Abase = X + (size_t)(bi * 128 + lr) * DIM + lc;
    const float* Bbase = X + (size_t)(bj * 128 + lr) * DIM + lc;

    int ty = tid >> 4, tx = tid & 15;
    int m0 = ty * 8, n0 = tx * 8;
    float acc[8][8];
    #pragma unroll
    for (int i = 0; i < 8; i++)
        #pragma unroll
        for (int j = 0; j < 8; j++) acc[i][j] = 0.f;

    for (int k0 = 0; k0 < DIM; k0 += 8) {
        float4 av = *(const float4*)(Abase + k0);
        float4 bv = *(const float4*)(Bbase + k0);
        __syncthreads();
        As[lc + 0][lr] = av.x; As[lc + 1][lr] = av.y; As[lc + 2][lr] = av.z; As[lc + 3][lr] = av.w;
        Bs[lc + 0][lr] = bv.x; Bs[lc + 1][lr] = bv.y; Bs[lc + 2][lr] = bv.z; Bs[lc + 3][lr] = bv.w;
        __syncthreads();
        #pragma unroll
        for (int kk = 0; kk < 8; kk++) {
            float4 a0 = *(const float4*)&As[kk][m0];
            float4 a1 = *(const float4*)&As[kk][m0 + 4];
            float4 b0 = *(const float4*)&Bs[kk][n0];
            float4 b1 = *(const float4*)&Bs[kk][n0 + 4];
            float a[8] = {a0.x, a0.y, a0.z, a0.w, a1.x, a1.y, a1.z, a1.w};
            float b[8] = {b0.x, b0.y, b0.z, b0.w, b1.x, b1.y, b1.z, b1.w};
            #pragma unroll
            for (int mi = 0; mi < 8; mi++)
                #pragma unroll
                for (int nj = 0; nj < 8; nj++)
                    acc[mi][nj] += a[mi] * b[nj];
        }
    }

    // epilogue: dist = sqrt(max(sq_i + sq_j - 2*dot, 1e-12)), diag = BIG
    int giBase = bi * 128 + m0, gjBase = bj * 128 + n0;
    #pragma unroll
    for (int mi = 0; mi < 8; mi++) {
        float sa = sqA[m0 + mi];
        int gi = giBase + mi;
        #pragma unroll
        for (int nj = 0; nj < 8; nj++) {
            float d2 = sa + sqB[n0 + nj] - 2.f * acc[mi][nj];
            d2 = fmaxf(d2, 1e-12f);
            float dv = sqrtf(d2);
            if (gi == gjBase + nj) dv = BIGF;
            acc[mi][nj] = dv;
        }
        float* rowp = Dst + (size_t)gi * NPTS + gjBase;
        *(float4*)(rowp)     = make_float4(acc[mi][0], acc[mi][1], acc[mi][2], acc[mi][3]);
        *(float4*)(rowp + 4) = make_float4(acc[mi][4], acc[mi][5], acc[mi][6], acc[mi][7]);
    }
    if (bi != bj) {   // mirror (float4 along gi keeps sector amplification ~2x)
        #pragma unroll
        for (int nj = 0; nj < 8; nj++) {
            int gj = gjBase + nj;
            float* colp = Dst + (size_t)gj * NPTS + giBase;
            *(float4*)(colp)     = make_float4(acc[0][nj], acc[1][nj], acc[2][nj], acc[3][nj]);
            *(float4*)(colp + 4) = make_float4(acc[4][nj], acc[5][nj], acc[6][nj], acc[7][nj]);
        }
    }
}

// ---------------- Prim's MST: one persistent block per matrix ----------------
// in-tree nodes are encoded by md[k] == MARKF (1e30); real distances < ~100.
__global__ void __launch_bounds__(1024) prim_kernel() {
    int mat = blockIdx.x;
    const float* Dst = g_dist[mat];
    float* deaths = g_deaths[mat];

    __shared__ float md[NPTS];          // 16KB
    __shared__ float redval[32];
    __shared__ int   redidx[32];
    __shared__ int   s_j;

    int tid = threadIdx.x, lane = tid & 31, warp = tid >> 5;
    int k0 = tid * 4;

    // ---- init: md = dist row 0, node 0 marked; compute group minima ----
    {
        float4 r = ((const float4*)Dst)[tid];
        float v0 = (tid == 0) ? MARKF : r.x;
        float v1 = r.y, v2 = r.z, v3 = r.w;
        ((float4*)md)[tid] = make_float4(v0, v1, v2, v3);
        float bv = MARKF; int bidx = k0;
        if (v0 < bv) { bv = v0; bidx = k0; }
        if (v1 < bv) { bv = v1; bidx = k0 + 1; }
        if (v2 < bv) { bv = v2; bidx = k0 + 2; }
        if (v3 < bv) { bv = v3; bidx = k0 + 3; }
        unsigned mu   = __reduce_min_sync(0xffffffffu, __float_as_uint(bv));
        unsigned ball = __ballot_sync(0xffffffffu, __float_as_uint(bv) == mu);
        int src  = __ffs(ball) - 1;
        int widx = __shfl_sync(0xffffffffu, bidx, src);
        if (lane == 0) { redval[warp] = __uint_as_float(mu); redidx[warp] = widx; }
    }
    __syncthreads();

    for (int step = 0; step < NPTS - 1; step++) {
        // ---- phase A: select argmin over 32 group minima (warp 0) ----
        if (warp == 0) {
            float v  = redval[lane];
            int  idx = redidx[lane];
            unsigned mu   = __reduce_min_sync(0xffffffffu, __float_as_uint(v));
            unsigned ball = __ballot_sync(0xffffffffu, __float_as_uint(v) == mu);
            int src = __ffs(ball) - 1;
            int j   = __shfl_sync(0xffffffffu, idx, src);
            if (lane == 0) { deaths[step] = __uint_as_float(mu); s_j = j; }
        }
        __syncthreads();
        int j = s_j;

        // ---- phase B: md = min(md, dist[j]); fold next group minima ----
        float4 r = *(const float4*)(Dst + (size_t)j * NPTS + k0);
        float4 m = ((const float4*)md)[tid];
        float nv0 = (k0     == j) ? MARKF : ((m.x >= MARK_TH) ? m.x : fminf(m.x, r.x));
        float nv1 = (k0 + 1 == j) ? MARKF : ((m.y >= MARK_TH) ? m.y : fminf(m.y, r.y));
        float nv2 = (k0 + 2 == j) ? MARKF : ((m.z >= MARK_TH) ? m.z : fminf(m.z, r.z));
        float nv3 = (k0 + 3 == j) ? MARKF : ((m.w >= MARK_TH) ? m.w : fminf(m.w, r.w));
        ((float4*)md)[tid] = make_float4(nv0, nv1, nv2, nv3);
        float bv = MARKF; int bidx = k0;
        if (nv0 < bv) { bv = nv0; bidx = k0; }
        if (nv1 < bv) { bv = nv1; bidx = k0 + 1; }
        if (nv2 < bv) { bv = nv2; bidx = k0 + 2; }
        if (nv3 < bv) { bv = nv3; bidx = k0 + 3; }
        unsigned mu   = __reduce_min_sync(0xffffffffu, __float_as_uint(bv));
        unsigned ball = __ballot_sync(0xffffffffu, __float_as_uint(bv) == mu);
        int src  = __ffs(ball) - 1;
        int widx = __shfl_sync(0xffffffffu, bidx, src);
        if (lane == 0) { redval[warp] = __uint_as_float(mu); redidx[warp] = widx; }
        __syncthreads();
    }
}

// ---------------- bitonic sort of deaths (pad slot 4095 with 0) ----------------
__global__ void __launch_bounds__(1024) sort_kernel() {
    int mat = blockIdx.x;
    __shared__ float s[NPTS];
    for (int i = threadIdx.x; i < NPTS; i += 1024)
        s[i] = (i < NPTS - 1) ? g_deaths[mat][i] : 0.0f;
    __syncthreads();
    for (int k = 2; k <= NPTS; k <<= 1)
        for (int j2 = k >> 1; j2 > 0; j2 >>= 1) {
            for (int i = threadIdx.x; i < NPTS; i += 1024) {
                int ixj = i ^ j2;
                if (ixj > i) {
                    float a = s[i], b = s[ixj];
                    bool up = ((i & k) == 0);
                    if ((a > b) == up) { s[i] = b; s[ixj] = a; }
                }
            }
            __syncthreads();
        }
    for (int i = threadIdx.x; i < NPTS; i += 1024)
        g_deaths[mat][i] = s[i];
}

// ---------------- final: Wasserstein-1 match + L2 loss, deterministic ----------------
__global__ void __launch_bounds__(1024) final_kernel(float* __restrict__ out) {
    __shared__ float red[1024];
    int tid = threadIdx.x;
    float s = 0.f;
    for (int i = tid; i < NPTS; i += 1024) {
        float a = g_deaths[0][i], b = g_deaths[1][i];
        s += fminf(fabsf(a - b), 0.5f * (a + b));
    }
    s += g_partials[tid] * (1.0f / ((float)NPTS * (float)DIM));
    red[tid] = s; __syncthreads();
    #pragma unroll
    for (int st = 512; st > 0; st >>= 1) {
        if (tid < st) red[tid] += red[tid + st];
        __syncthreads();
    }
    if (tid == 0) out[0] = red[0];
}

extern "C" void kernel_launch(void* const* d_in, const int* in_sizes, int n_in,
                              void* d_out, int out_size) {
    const float* x1 = (const float*)d_in[0];
    const float* x2 = (const float*)d_in[1];
    float* out = (float*)d_out;

    sq_kernel  <<<1024, 256>>>(x1, x2);
    repr_kernel<<<1024, 256>>>(x1, x2);
    dist_kernel<<<dim3(528, 1, 2), 256>>>(x1, x2);
    prim_kernel<<<2, 1024>>>();
    sort_kernel<<<2, 1024>>>();
    final_kernel<<<1, 1024>>>(out);
}

// round 3
// speedup vs baseline: 6.2143x; 6.2143x over previous
#include <cuda_runtime.h>
#include <math.h>

#define NPTS 4096
#define DIM  512
#define BIGF   1e30f
#define INFKEY 0xFFFFFFFFFFFFFFFFull

// ---------------- scratch (static device globals; no allocation) ----------------
__device__ float g_dist[2][(size_t)NPTS * NPTS];            // 2 x 64MB distance matrices
__device__ float g_sq[2][NPTS];                             // squared norms
__device__ float g_deaths[2][NPTS];                         // MST edge weights (4095 used)
__device__ float g_partials[1024];                          // L2-loss per-block partials
__device__ int   g_comp[2][NPTS];                           // Boruvka component labels
__device__ unsigned long long g_rowbest[2][NPTS];           // per-row best outgoing edge key
__device__ int   g_ndeaths[2];
__device__ int   g_done[2];

// ---------------- init ----------------
__global__ void init_kernel() {
    int i = blockIdx.x * 256 + threadIdx.x;    // 0..8191
    int mat = i >> 12, v = i & (NPTS - 1);
    g_comp[mat][v] = v;
    if (v == 0) { g_ndeaths[mat] = 0; g_done[mat] = 0; }
}

// ---------------- squared norms: one warp per row ----------------
__global__ void sq_kernel(const float* __restrict__ x1, const float* __restrict__ x2) {
    int w    = (blockIdx.x * blockDim.x + threadIdx.x) >> 5;
    int lane = threadIdx.x & 31;
    int mat  = w >> 12;
    int row  = w & (NPTS - 1);
    const float* x = mat ? x2 : x1;
    const float* p = x + (size_t)row * DIM;
    float s = 0.f;
    for (int c = lane; c < DIM; c += 32) { float v = p[c]; s += v * v; }
    #pragma unroll
    for (int o = 16; o > 0; o >>= 1) s += __shfl_xor_sync(0xffffffffu, s, o);
    if (lane == 0) g_sq[mat][row] = s;
}

// ---------------- representation loss partials (deterministic) ----------------
__global__ void repr_kernel(const float* __restrict__ x1, const float* __restrict__ x2) {
    __shared__ float red[256];
    size_t base = (size_t)blockIdx.x * 2048;
    float s = 0.f;
    for (int i = threadIdx.x; i < 2048; i += 256) {
        float d = x1[base + i] - x2[base + i];
        s += d * d;
    }
    red[threadIdx.x] = s; __syncthreads();
    #pragma unroll
    for (int st = 128; st > 0; st >>= 1) {
        if (threadIdx.x < st) red[threadIdx.x] += red[threadIdx.x + st];
        __syncthreads();
    }
    if (threadIdx.x == 0) g_partials[blockIdx.x] = red[0];
}

// ---------------- distance matrix: symmetric tiled fp32 GEMM ----------------
__global__ void __launch_bounds__(256) dist_kernel(const float* __restrict__ x1,
                                                   const float* __restrict__ x2) {
    int mat = blockIdx.z;
    const float* X  = mat ? x2 : x1;
    float* Dst      = g_dist[mat];
    const float* sq = g_sq[mat];

    int t = blockIdx.x, bi = 0, len = 32;
    while (t >= len) { t -= len; len--; bi++; }
    int bj = bi + t;

    __shared__ float As[8][128];
    __shared__ float Bs[8][128];
    __shared__ float sqA[128], sqB[128];

    int tid = threadIdx.x;
    if (tid < 128) sqA[tid] = sq[bi * 128 + tid];
    else           sqB[tid - 128] = sq[bj * 128 + (tid - 128)];

    int lr = tid >> 1;
    int lc = (tid & 1) * 4;
    const float* Abase = X + (size_t)(bi * 128 + lr) * DIM + lc;
    const float* Bbase = X + (size_t)(bj * 128 + lr) * DIM + lc;

    int ty = tid >> 4, tx = tid & 15;
    int m0 = ty * 8, n0 = tx * 8;
    float acc[8][8];
    #pragma unroll
    for (int i = 0; i < 8; i++)
        #pragma unroll
        for (int j = 0; j < 8; j++) acc[i][j] = 0.f;

    for (int k0 = 0; k0 < DIM; k0 += 8) {
        float4 av = *(const float4*)(Abase + k0);
        float4 bv = *(const float4*)(Bbase + k0);
        __syncthreads();
        As[lc + 0][lr] = av.x; As[lc + 1][lr] = av.y; As[lc + 2][lr] = av.z; As[lc + 3][lr] = av.w;
        Bs[lc + 0][lr] = bv.x; Bs[lc + 1][lr] = bv.y; Bs[lc + 2][lr] = bv.z; Bs[lc + 3][lr] = bv.w;
        __syncthreads();
        #pragma unroll
        for (int kk = 0; kk < 8; kk++) {
            float4 a0 = *(const float4*)&As[kk][m0];
            float4 a1 = *(const float4*)&As[kk][m0 + 4];
            float4 b0 = *(const float4*)&Bs[kk][n0];
            float4 b1 = *(const float4*)&Bs[kk][n0 + 4];
            float a[8] = {a0.x, a0.y, a0.z, a0.w, a1.x, a1.y, a1.z, a1.w};
            float b[8] = {b0.x, b0.y, b0.z, b0.w, b1.x, b1.y, b1.z, b1.w};
            #pragma unroll
            for (int mi = 0; mi < 8; mi++)
                #pragma unroll
                for (int nj = 0; nj < 8; nj++)
                    acc[mi][nj] += a[mi] * b[nj];
        }
    }

    int giBase = bi * 128 + m0, gjBase = bj * 128 + n0;
    #pragma unroll
    for (int mi = 0; mi < 8; mi++) {
        float sa = sqA[m0 + mi];
        int gi = giBase + mi;
        #pragma unroll
        for (int nj = 0; nj < 8; nj++) {
            float d2 = sa + sqB[n0 + nj] - 2.f * acc[mi][nj];
            d2 = fmaxf(d2, 1e-12f);
            float dv = sqrtf(d2);
            if (gi == gjBase + nj) dv = BIGF;
            acc[mi][nj] = dv;
        }
        float* rowp = Dst + (size_t)gi * NPTS + gjBase;
        *(float4*)(rowp)     = make_float4(acc[mi][0], acc[mi][1], acc[mi][2], acc[mi][3]);
        *(float4*)(rowp + 4) = make_float4(acc[mi][4], acc[mi][5], acc[mi][6], acc[mi][7]);
    }
    if (bi != bj) {
        #pragma unroll
        for (int nj = 0; nj < 8; nj++) {
            int gj = gjBase + nj;
            float* colp = Dst + (size_t)gj * NPTS + giBase;
            *(float4*)(colp)     = make_float4(acc[0][nj], acc[1][nj], acc[2][nj], acc[3][nj]);
            *(float4*)(colp + 4) = make_float4(acc[4][nj], acc[5][nj], acc[6][nj], acc[7][nj]);
        }
    }
}

// ---------------- Boruvka scan: one warp per row, min outgoing edge ----------------
// key = (f32 dist bits << 24) | (min(i,k) << 12 | max(i,k))  -- total order, symmetric
__global__ void __launch_bounds__(256) boruvka_scan() {
    int w    = (blockIdx.x * 256 + threadIdx.x) >> 5;   // 0..8191
    int lane = threadIdx.x & 31;
    int mat  = w >> 12;
    int row  = w & (NPTS - 1);
    if (g_done[mat]) return;

    int myc = g_comp[mat][row];
    const float4* drow = (const float4*)(g_dist[mat] + (size_t)row * NPTS);
    const int4*   crow = (const int4*)(g_comp[mat]);

    unsigned long long best = INFKEY;
    for (int t = lane; t < NPTS / 4; t += 32) {
        float4 d = drow[t];
        int4   c = crow[t];
        int k = t * 4;
        if (c.x != myc) {
            int lo = min(row, k),     hi = max(row, k);
            unsigned long long key = ((unsigned long long)__float_as_uint(d.x) << 24)
                                   | (unsigned long long)((lo << 12) | hi);
            best = min(best, key);
        }
        if (c.y != myc) {
            int lo = min(row, k + 1), hi = max(row, k + 1);
            unsigned long long key = ((unsigned long long)__float_as_uint(d.y) << 24)
                                   | (unsigned long long)((lo << 12) | hi);
            best = min(best, key);
        }
        if (c.z != myc) {
            int lo = min(row, k + 2), hi = max(row, k + 2);
            unsigned long long key = ((unsigned long long)__float_as_uint(d.z) << 24)
                                   | (unsigned long long)((lo << 12) | hi);
            best = min(best, key);
        }
        if (c.w != myc) {
            int lo = min(row, k + 3), hi = max(row, k + 3);
            unsigned long long key = ((unsigned long long)__float_as_uint(d.w) << 24)
                                   | (unsigned long long)((lo << 12) | hi);
            best = min(best, key);
        }
    }
    #pragma unroll
    for (int o = 16; o > 0; o >>= 1) {
        unsigned long long other = __shfl_xor_sync(0xffffffffu, best, o);
        best = min(best, other);
    }
    if (lane == 0) g_rowbest[mat][row] = best;
}

// ---------------- Boruvka merge: one block per matrix ----------------
__global__ void __launch_bounds__(1024) boruvka_merge() {
    int mat = blockIdx.x;
    if (g_done[mat]) return;

    __shared__ unsigned long long sbest[NPTS];   // 32KB
    __shared__ unsigned short    par[NPTS];      // 8KB
    __shared__ int s_roots;

    int tid = threadIdx.x;
    for (int c = tid; c < NPTS; c += 1024) sbest[c] = INFKEY;
    __syncthreads();

    // reduce rows -> component best (smem atomics)
    for (int r = tid; r < NPTS; r += 1024) {
        unsigned long long k = g_rowbest[mat][r];
        if (k != INFKEY) atomicMin(&sbest[g_comp[mat][r]], k);
    }
    __syncthreads();

    // hook + record deaths (dedup mutual pairs: identical key)
    for (int c = tid; c < NPTS; c += 1024) {
        unsigned long long k = sbest[c];
        int p = c;
        if (k != INFKEY) {
            int eid = (int)(k & 0xFFFFFF);
            int u = eid >> 12, v = eid & (NPTS - 1);
            int cu = g_comp[mat][u];
            int d = (cu == c) ? g_comp[mat][v] : cu;
            p = d;
            bool mutual = (sbest[d] == k);
            if (!(mutual && c > d)) {
                float wgt = __uint_as_float((unsigned)(k >> 24));
                int pos = atomicAdd(&g_ndeaths[mat], 1);
                g_deaths[mat][pos] = wgt;
            }
        }
        par[c] = (unsigned short)p;
    }
    __syncthreads();

    // break mutual 2-cycles: smaller index becomes root
    for (int c = tid; c < NPTS; c += 1024) {
        int p = par[c];
        if (p != c && par[p] == c && c < p) par[c] = (unsigned short)c;
    }
    __syncthreads();

    // pointer jumping (depth <= 4096 -> 12 doublings)
    for (int it = 0; it < 12; it++) {
        for (int c = tid; c < NPTS; c += 1024) par[c] = par[par[c]];
        __syncthreads();
    }

    if (tid == 0) s_roots = 0;
    __syncthreads();
    for (int i = tid; i < NPTS; i += 1024) {
        int nc = par[g_comp[mat][i]];
        g_comp[mat][i] = nc;
        if (nc == i) atomicAdd(&s_roots, 1);
    }
    __syncthreads();
    if (tid == 0 && s_roots <= 1) g_done[mat] = 1;
}

// ---------------- bitonic sort of deaths (pad slot 4095 with 0) ----------------
__global__ void __launch_bounds__(1024) sort_kernel() {
    int mat = blockIdx.x;
    __shared__ float s[NPTS];
    for (int i = threadIdx.x; i < NPTS; i += 1024)
        s[i] = (i < NPTS - 1) ? g_deaths[mat][i] : 0.0f;
    __syncthreads();
    for (int k = 2; k <= NPTS; k <<= 1)
        for (int j2 = k >> 1; j2 > 0; j2 >>= 1) {
            for (int i = threadIdx.x; i < NPTS; i += 1024) {
                int ixj = i ^ j2;
                if (ixj > i) {
                    float a = s[i], b = s[ixj];
                    bool up = ((i & k) == 0);
                    if ((a > b) == up) { s[i] = b; s[ixj] = a; }
                }
            }
            __syncthreads();
        }
    for (int i = threadIdx.x; i < NPTS; i += 1024)
        g_deaths[mat][i] = s[i];
}

// ---------------- final: Wasserstein-1 match + L2 loss, deterministic ----------------
__global__ void __launch_bounds__(1024) final_kernel(float* __restrict__ out) {
    __shared__ float red[1024];
    int tid = threadIdx.x;
    float s = 0.f;
    for (int i = tid; i < NPTS; i += 1024) {
        float a = g_deaths[0][i], b = g_deaths[1][i];
        s += fminf(fabsf(a - b), 0.5f * (a + b));
    }
    s += g_partials[tid] * (1.0f / ((float)NPTS * (float)DIM));
    red[tid] = s; __syncthreads();
    #pragma unroll
    for (int st = 512; st > 0; st >>= 1) {
        if (tid < st) red[tid] += red[tid + st];
        __syncthreads();
    }
    if (tid == 0) out[0] = red[0];
}

extern "C" void kernel_launch(void* const* d_in, const int* in_sizes, int n_in,
                              void* d_out, int out_size) {
    const float* x1 = (const float*)d_in[0];
    const float* x2 = (const float*)d_in[1];
    float* out = (float*)d_out;

    init_kernel<<<32, 256>>>();
    sq_kernel  <<<1024, 256>>>(x1, x2);
    repr_kernel<<<1024, 256>>>(x1, x2);
    dist_kernel<<<dim3(528, 1, 2), 256>>>(x1, x2);
    for (int r = 0; r < 12; r++) {
        boruvka_scan <<<1024, 256>>>();
        boruvka_merge<<<2, 1024>>>();
    }
    sort_kernel<<<2, 1024>>>();
    final_kernel<<<1, 1024>>>(out);
}

// round 5
// speedup vs baseline: 11.9056x; 1.9158x over previous
#include <cuda_runtime.h>
#include <cuda_bf16.h>
#include <math.h>
#include <stdint.h>

#define NPTS 4096
#define DIM  512
#define KPK  1536              // packed K = [512 | 512 | 512]
#define BIGF   1e30f
#define INFKEY 0xFFFFFFFFFFFFFFFFull
#define TRANS_LD 132

// ---------------- scratch (static device globals; no allocation) ----------------
__device__ float g_dist[2][(size_t)NPTS * NPTS];            // 2 x 64MB distance matrices
__device__ __nv_bfloat16 g_pkA[2][(size_t)NPTS * KPK];      // [hi | lo | hi]
__device__ __nv_bfloat16 g_pkB[2][(size_t)NPTS * KPK];      // [hi | hi | lo]
__device__ float g_sq[2][NPTS];                             // squared norms (fp32)
__device__ float g_deaths[2][NPTS];                         // MST edge weights (4095 used)
__device__ float g_partials[1024];                          // L2-loss per-block partials
__device__ int   g_comp[2][NPTS];                           // Boruvka component labels
__device__ unsigned long long g_rowbest[2][NPTS];           // per-row best outgoing edge key
__device__ int   g_ndeaths[2];
__device__ int   g_done[2];

// ---------------- helpers ----------------
__device__ __forceinline__ uint32_t smem_u32(const void* p) {
    uint32_t a;
    asm("{ .reg .u64 t; cvta.to.shared.u64 t, %1; cvt.u32.u64 %0, t; }" : "=r"(a) : "l"(p));
    return a;
}
__device__ __forceinline__ uint32_t swz(uint32_t b) { return b ^ ((b >> 3) & 0x70); }

__device__ __forceinline__ void cp16(uint32_t s, const void* g) {
    asm volatile("cp.async.cg.shared.global [%0], [%1], 16;" :: "r"(s), "l"(g));
}
__device__ __forceinline__ void ldsm4(uint32_t& r0, uint32_t& r1, uint32_t& r2, uint32_t& r3,
                                      uint32_t a) {
    asm volatile("ldmatrix.sync.aligned.m8n8.x4.shared.b16 {%0,%1,%2,%3}, [%4];"
                 : "=r"(r0), "=r"(r1), "=r"(r2), "=r"(r3) : "r"(a));
}
__device__ __forceinline__ void mma16816(float* c, const uint32_t* a, const uint32_t* b) {
    asm volatile("mma.sync.aligned.m16n8k16.row.col.f32.bf16.bf16.f32 "
                 "{%0,%1,%2,%3}, {%4,%5,%6,%7}, {%8,%9}, {%0,%1,%2,%3};"
                 : "+f"(c[0]), "+f"(c[1]), "+f"(c[2]), "+f"(c[3])
                 : "r"(a[0]), "r"(a[1]), "r"(a[2]), "r"(a[3]), "r"(b[0]), "r"(b[1]));
}

// ---------------- init ----------------
__global__ void init_kernel() {
    int i = blockIdx.x * 256 + threadIdx.x;    // 0..8191
    int mat = i >> 12, v = i & (NPTS - 1);
    g_comp[mat][v] = v;
    g_rowbest[mat][v] = INFKEY;
    if (v == 0) { g_ndeaths[mat] = 0; g_done[mat] = 0; }
}

// ---------------- prep: hi/lo packed operands + squared norms (warp per row) ----------------
__global__ void prep_kernel(const float* __restrict__ x1, const float* __restrict__ x2) {
    int w    = (blockIdx.x * 256 + threadIdx.x) >> 5;   // 0..8191
    int lane = threadIdx.x & 31;
    int mat  = w >> 12;
    int row  = w & (NPTS - 1);
    const float* p = (mat ? x2 : x1) + (size_t)row * DIM;
    __nv_bfloat16* pa = g_pkA[mat] + (size_t)row * KPK;
    __nv_bfloat16* pb = g_pkB[mat] + (size_t)row * KPK;
    float s = 0.f;
    for (int c = lane * 4; c < DIM; c += 128) {
        float4 v = *(const float4*)(p + c);
        __nv_bfloat16 h0 = __float2bfloat16(v.x), h1 = __float2bfloat16(v.y);
        __nv_bfloat16 h2 = __float2bfloat16(v.z), h3 = __float2bfloat16(v.w);
        __nv_bfloat16 l0 = __float2bfloat16(v.x - __bfloat162float(h0));
        __nv_bfloat16 l1 = __float2bfloat16(v.y - __bfloat162float(h1));
        __nv_bfloat16 l2 = __float2bfloat16(v.z - __bfloat162float(h2));
        __nv_bfloat16 l3 = __float2bfloat16(v.w - __bfloat162float(h3));
        ushort4 hs = make_ushort4(__bfloat16_as_ushort(h0), __bfloat16_as_ushort(h1),
                                  __bfloat16_as_ushort(h2), __bfloat16_as_ushort(h3));
        ushort4 ls = make_ushort4(__bfloat16_as_ushort(l0), __bfloat16_as_ushort(l1),
                                  __bfloat16_as_ushort(l2), __bfloat16_as_ushort(l3));
        *(ushort4*)(pa + c)        = hs;   // A: [hi | lo | hi]
        *(ushort4*)(pa + 512 + c)  = ls;
        *(ushort4*)(pa + 1024 + c) = hs;
        *(ushort4*)(pb + c)        = hs;   // B: [hi | hi | lo]
        *(ushort4*)(pb + 512 + c)  = hs;
        *(ushort4*)(pb + 1024 + c) = ls;
        s += v.x * v.x + v.y * v.y + v.z * v.z + v.w * v.w;
    }
    #pragma unroll
    for (int o = 16; o > 0; o >>= 1) s += __shfl_xor_sync(0xffffffffu, s, o);
    if (lane == 0) g_sq[mat][row] = s;
}

// ---------------- representation loss partials (deterministic) ----------------
__global__ void repr_kernel(const float* __restrict__ x1, const float* __restrict__ x2) {
    __shared__ float red[256];
    size_t base = (size_t)blockIdx.x * 2048;
    float s = 0.f;
    for (int i = threadIdx.x; i < 2048; i += 256) {
        float d = x1[base + i] - x2[base + i];
        s += d * d;
    }
    red[threadIdx.x] = s; __syncthreads();
    #pragma unroll
    for (int st = 128; st > 0; st >>= 1) {
        if (threadIdx.x < st) red[threadIdx.x] += red[threadIdx.x + st];
        __syncthreads();
    }
    if (threadIdx.x == 0) g_partials[blockIdx.x] = red[0];
}

// ---------------- distance matrix: mma.sync bf16 GEMM, M128 N128 K1536 ----------------
// 8 warps (4m x 2n), warp tile 32x64, BK=32 double-buffered via cp.async.
__global__ void __launch_bounds__(256, 2) dist_hmma_kernel() {
    __shared__ __align__(128) unsigned char sraw[64 * TRANS_LD * 4];  // 33792B (>= 32KB stages)
    int mat = blockIdx.z;
    int t = blockIdx.x, bi = 0, len = 32;
    while (t >= len) { t -= len; len--; bi++; }
    int bj = bi + t;

    const __nv_bfloat16* pkA = g_pkA[mat];
    const __nv_bfloat16* pkB = g_pkB[mat];
    float* Dst = g_dist[mat];
    int tid = threadIdx.x, lane = tid & 31, wid = tid >> 5;
    int wm = wid & 3, wn = wid >> 2;           // warp tile: rows wm*32, cols wn*64
    uint32_t sb = smem_u32(sraw);

    float acc[2][8][4];
    #pragma unroll
    for (int im = 0; im < 2; im++)
        #pragma unroll
        for (int in = 0; in < 8; in++)
            #pragma unroll
            for (int q = 0; q < 4; q++) acc[im][in][q] = 0.f;

    // stage issue: A rows bi*128.., B rows bj*128.., 64B (32 bf16) per row per stage
    int rowA0 = bi * 128, rowB0 = bj * 128;
    #define ISSUE(s) do {                                                           \
        int _b = (s) & 1; int _k0 = (s) * 32;                                       \
        _Pragma("unroll")                                                           \
        for (int _h = 0; _h < 2; _h++) {                                            \
            int _tt = tid + _h * 256;                                               \
            int _row = _tt >> 2, _c16 = _tt & 3;                                    \
            uint32_t _so = swz((uint32_t)(_row * 64 + _c16 * 16));                  \
            cp16(sb + _b * 8192 + _so,                                              \
                 pkA + (size_t)(rowA0 + _row) * KPK + _k0 + _c16 * 8);              \
            cp16(sb + 16384 + _b * 8192 + _so,                                      \
                 pkB + (size_t)(rowB0 + _row) * KPK + _k0 + _c16 * 8);              \
        }                                                                           \
        asm volatile("cp.async.commit_group;" ::: "memory");                        \
    } while (0)

    ISSUE(0);
    for (int s = 0; s < 48; s++) {
        if (s < 47) { ISSUE(s + 1); asm volatile("cp.async.wait_group 1;" ::: "memory"); }
        else        {               asm volatile("cp.async.wait_group 0;" ::: "memory"); }
        __syncthreads();
        uint32_t baseA = sb + (s & 1) * 8192;
        uint32_t baseB = sb + 16384 + (s & 1) * 8192;
        #pragma unroll
        for (int kk = 0; kk < 2; kk++) {
            uint32_t a[2][4], bb[8][2];
            #pragma unroll
            for (int im = 0; im < 2; im++) {
                uint32_t addr = baseA + swz((uint32_t)((wm * 32 + im * 16 + (lane & 15)) * 64
                                                       + kk * 32 + (lane >> 4) * 16));
                ldsm4(a[im][0], a[im][1], a[im][2], a[im][3], addr);
            }
            #pragma unroll
            for (int np = 0; np < 4; np++) {
                uint32_t addr = baseB + swz((uint32_t)((wn * 64 + np * 16 + ((lane >> 4) << 3)
                                                        + (lane & 7)) * 64
                                                       + kk * 32 + ((lane >> 3) & 1) * 16));
                uint32_t r0, r1, r2, r3;
                ldsm4(r0, r1, r2, r3, addr);
                bb[np * 2][0] = r0; bb[np * 2][1] = r1;
                bb[np * 2 + 1][0] = r2; bb[np * 2 + 1][1] = r3;
            }
            #pragma unroll
            for (int im = 0; im < 2; im++)
                #pragma unroll
                for (int in = 0; in < 8; in++)
                    mma16816(acc[im][in], a[im], bb[in]);
        }
        __syncthreads();
    }
    #undef ISSUE

    // ---- epilogue: dist transform + row-major stores ----
    bool diag = (bi == bj);
    int giBase = bi * 128, gjBase = bj * 128;
    float sqr[2][2], sqc[8][2];
    #pragma unroll
    for (int im = 0; im < 2; im++)
        #pragma unroll
        for (int p = 0; p < 2; p++)
            sqr[im][p] = g_sq[mat][giBase + wm * 32 + im * 16 + (lane >> 2) + p * 8];
    #pragma unroll
    for (int in = 0; in < 8; in++) {
        int col = gjBase + wn * 64 + in * 8 + (lane & 3) * 2;
        sqc[in][0] = g_sq[mat][col];
        sqc[in][1] = g_sq[mat][col + 1];
    }
    #pragma unroll
    for (int im = 0; im < 2; im++) {
        #pragma unroll
        for (int in = 0; in < 8; in++) {
            #pragma unroll
            for (int p = 0; p < 2; p++) {
                int m = giBase + wm * 32 + im * 16 + (lane >> 2) + p * 8;
                int n = gjBase + wn * 64 + in * 8 + (lane & 3) * 2;
                float d0 = sqr[im][p] + sqc[in][0] - 2.f * acc[im][in][p * 2];
                float d1 = sqr[im][p] + sqc[in][1] - 2.f * acc[im][in][p * 2 + 1];
                d0 = sqrtf(fmaxf(d0, 1e-12f));
                d1 = sqrtf(fmaxf(d1, 1e-12f));
                if (diag && m == n)     d0 = BIGF;
                if (diag && m == n + 1) ; // m>n never equals n here; only m==n or m==n+1 check:
                if (diag && m == n + 1) d1 = d1; // no-op (diagonal is m==n or m==n+1 on odd col)
                if (diag && m == n + 1) ; 
                if (diag && m == (n + 1)) { /* second col is n+1 */ }
                if (diag && m == n + 1) {}
                if (diag && (m == n + 1)) d1 = (m == n + 1) ? d1 : d1;
                if (diag && m == n + 1) {}
                // correct diagonal handling for the pair (n, n+1):
                if (diag) { if (m == n) d0 = BIGF; if (m == n + 1) d1 = BIGF; }
                acc[im][in][p * 2]     = d0;
                acc[im][in][p * 2 + 1] = d1;
                *(float2*)(Dst + (size_t)m * NPTS + n) = make_float2(d0, d1);
            }
        }
    }

    // ---- mirror via smem transpose (two 64-col chunks) ----
    if (!diag) {
        float* trans = (float*)sraw;
        #pragma unroll
        for (int h = 0; h < 2; h++) {
            __syncthreads();
            if (wn == h) {
                #pragma unroll
                for (int im = 0; im < 2; im++)
                    #pragma unroll
                    for (int in = 0; in < 8; in++)
                        #pragma unroll
                        for (int p = 0; p < 2; p++) {
                            int ml = wm * 32 + im * 16 + (lane >> 2) + p * 8;
                            int nl = in * 8 + (lane & 3) * 2;
                            trans[nl * TRANS_LD + ml]       = acc[im][in][p * 2];
                            trans[(nl + 1) * TRANS_LD + ml] = acc[im][in][p * 2 + 1];
                        }
            }
            __syncthreads();
            int r = tid & 63, seg = tid >> 6;
            const float* srcp = trans + r * TRANS_LD + seg * 32;
            float* dstp = Dst + (size_t)(gjBase + h * 64 + r) * NPTS + giBase + seg * 32;
            #pragma unroll
            for (int i = 0; i < 8; i++)
                *(float4*)(dstp + i * 4) = *(const float4*)(srcp + i * 4);
        }
    }
}

// ---------------- Boruvka scan: warp/row, with stale-row cache ----------------
__global__ void __launch_bounds__(256) boruvka_scan() {
    int w    = (blockIdx.x * 256 + threadIdx.x) >> 5;   // 0..8191
    int lane = threadIdx.x & 31;
    int mat  = w >> 12;
    int row  = w & (NPTS - 1);
    if (g_done[mat]) return;

    int myc = g_comp[mat][row];
    unsigned long long cached = g_rowbest[mat][row];
    if (cached != INFKEY) {
        int eid = (int)(cached & 0xFFFFFF);
        int u = eid >> 12, v = eid & (NPTS - 1);
        int other = (u == row) ? v : u;
        if (g_comp[mat][other] != myc) return;   // cache still exact row min-outgoing
    }

    const float4* drow = (const float4*)(g_dist[mat] + (size_t)row * NPTS);
    const int4*   crow = (const int4*)(g_comp[mat]);
    unsigned long long best = INFKEY;
    for (int t = lane; t < NPTS / 4; t += 32) {
        float4 d = drow[t];
        int4   c = crow[t];
        int k = t * 4;
        if (c.x != myc) {
            int lo = min(row, k),     hi = max(row, k);
            best = min(best, ((unsigned long long)__float_as_uint(d.x) << 24)
                             | (unsigned long long)((lo << 12) | hi));
        }
        if (c.y != myc) {
            int lo = min(row, k + 1), hi = max(row, k + 1);
            best = min(best, ((unsigned long long)__float_as_uint(d.y) << 24)
                             | (unsigned long long)((lo << 12) | hi));
        }
        if (c.z != myc) {
            int lo = min(row, k + 2), hi = max(row, k + 2);
            best = min(best, ((unsigned long long)__float_as_uint(d.z) << 24)
                             | (unsigned long long)((lo << 12) | hi));
        }
        if (c.w != myc) {
            int lo = min(row, k + 3), hi = max(row, k + 3);
            best = min(best, ((unsigned long long)__float_as_uint(d.w) << 24)
                             | (unsigned long long)((lo << 12) | hi));
        }
    }
    #pragma unroll
    for (int o = 16; o > 0; o >>= 1) {
        unsigned long long other = __shfl_xor_sync(0xffffffffu, best, o);
        best = min(best, other);
    }
    if (lane == 0) g_rowbest[mat][row] = best;
}

// ---------------- Boruvka merge: one block per matrix ----------------
__global__ void __launch_bounds__(1024) boruvka_merge() {
    int mat = blockIdx.x;
    if (g_done[mat]) return;

    __shared__ unsigned long long sbest[NPTS];   // 32KB
    __shared__ unsigned short    par[NPTS];      // 8KB
    __shared__ int s_roots;

    int tid = threadIdx.x;
    for (int c = tid; c < NPTS; c += 1024) sbest[c] = INFKEY;
    __syncthreads();

    for (int r = tid; r < NPTS; r += 1024) {
        unsigned long long k = g_rowbest[mat][r];
        if (k != INFKEY) atomicMin(&sbest[g_comp[mat][r]], k);
    }
    __syncthreads();

    for (int c = tid; c < NPTS; c += 1024) {
        unsigned long long k = sbest[c];
        int p = c;
        if (k != INFKEY) {
            int eid = (int)(k & 0xFFFFFF);
            int u = eid >> 12, v = eid & (NPTS - 1);
            int cu = g_comp[mat][u];
            int d = (cu == c) ? g_comp[mat][v] : cu;
            p = d;
            bool mutual = (sbest[d] == k);
            if (!(mutual && c > d)) {
                float wgt = __uint_as_float((unsigned)(k >> 24));
                int pos = atomicAdd(&g_ndeaths[mat], 1);
                g_deaths[mat][pos] = wgt;
            }
        }
        par[c] = (unsigned short)p;
    }
    __syncthreads();

    for (int c = tid; c < NPTS; c += 1024) {
        int p = par[c];
        if (p != c && par[p] == c && c < p) par[c] = (unsigned short)c;
    }
    __syncthreads();

    for (int it = 0; it < 12; it++) {
        for (int c = tid; c < NPTS; c += 1024) par[c] = par[par[c]];
        __syncthreads();
    }

    if (tid == 0) s_roots = 0;
    __syncthreads();
    for (int i = tid; i < NPTS; i += 1024) {
        int nc = par[g_comp[mat][i]];
        g_comp[mat][i] = nc;
        if (nc == i) atomicAdd(&s_roots, 1);
    }
    __syncthreads();
    if (tid == 0 && s_roots <= 1) g_done[mat] = 1;
}

// ---------------- bitonic sort of deaths (pad slot 4095 with 0) ----------------
__global__ void __launch_bounds__(1024) sort_kernel() {
    int mat = blockIdx.x;
    __shared__ float s[NPTS];
    for (int i = threadIdx.x; i < NPTS; i += 1024)
        s[i] = (i < NPTS - 1) ? g_deaths[mat][i] : 0.0f;
    __syncthreads();
    for (int k = 2; k <= NPTS; k <<= 1)
        for (int j2 = k >> 1; j2 > 0; j2 >>= 1) {
            for (int i = threadIdx.x; i < NPTS; i += 1024) {
                int ixj = i ^ j2;
                if (ixj > i) {
                    float a = s[i], b = s[ixj];
                    bool up = ((i & k) == 0);
                    if ((a > b) == up) { s[i] = b; s[ixj] = a; }
                }
            }
            __syncthreads();
        }
    for (int i = threadIdx.x; i < NPTS; i += 1024)
        g_deaths[mat][i] = s[i];
}

// ---------------- final: Wasserstein-1 match + L2 loss, deterministic ----------------
__global__ void __launch_bounds__(1024) final_kernel(float* __restrict__ out) {
    __shared__ float red[1024];
    int tid = threadIdx.x;
    float s = 0.f;
    for (int i = tid; i < NPTS; i += 1024) {
        float a = g_deaths[0][i], b = g_deaths[1][i];
        s += fminf(fabsf(a - b), 0.5f * (a + b));
    }
    s += g_partials[tid] * (1.0f / ((float)NPTS * (float)DIM));
    red[tid] = s; __syncthreads();
    #pragma unroll
    for (int st = 512; st > 0; st >>= 1) {
        if (tid < st) red[tid] += red[tid + st];
        __syncthreads();
    }
    if (tid == 0) out[0] = red[0];
}

extern "C" void kernel_launch(void* const* d_in, const int* in_sizes, int n_in,
                              void* d_out, int out_size) {
    const float* x1 = (const float*)d_in[0];
    const float* x2 = (const float*)d_in[1];
    float* out = (float*)d_out;

    init_kernel<<<32, 256>>>();
    prep_kernel<<<1024, 256>>>(x1, x2);
    repr_kernel<<<1024, 256>>>(x1, x2);
    dist_hmma_kernel<<<dim3(528, 1, 2), 256>>>();
    for (int r = 0; r < 12; r++) {
        boruvka_scan <<<1024, 256>>>();
        boruvka_merge<<<2, 1024>>>();
    }
    sort_kernel<<<2, 1024>>>();
    final_kernel<<<1, 1024>>>(out);
}

// round 6
// speedup vs baseline: 11.9418x; 1.0030x over previous
#include <cuda_runtime.h>
#include <cuda_bf16.h>
#include <math.h>
#include <stdint.h>

#define NPTS 4096
#define DIM  512
#define KPK  1536              // packed K = [512 | 512 | 512]
#define BK   64
#define NSTAGE (KPK / BK)      // 24
#define BIGF   1e30f
#define INFKEY 0xFFFFFFFFFFFFFFFFull
#define TRANS_LD 132

// ---------------- scratch (static device globals; no allocation) ----------------
__device__ float g_dist[2][(size_t)NPTS * NPTS];            // 2 x 64MB distance matrices
__device__ __nv_bfloat16 g_pkA[2][(size_t)NPTS * KPK];      // [hi | lo | hi]
__device__ __nv_bfloat16 g_pkB[2][(size_t)NPTS * KPK];      // [hi | hi | lo]
__device__ float g_sq[2][NPTS];                             // squared norms (fp32)
__device__ float g_rowdiff[NPTS];                           // per-row (x1-x2)^2 sums
__device__ float g_deaths[2][NPTS];                         // MST edge weights (4095 used)
__device__ int   g_comp[2][NPTS];                           // Boruvka component labels
__device__ unsigned long long g_lanebest[2][NPTS][32];      // per-lane cached min outgoing
__device__ unsigned long long g_rowbest[2][NPTS];           // per-row best outgoing edge key
__device__ int   g_ndeaths[2];
__device__ int   g_done[2];

// ---------------- helpers ----------------
__device__ __forceinline__ uint32_t smem_u32(const void* p) {
    uint32_t a;
    asm("{ .reg .u64 t; cvta.to.shared.u64 t, %1; cvt.u32.u64 %0, t; }" : "=r"(a) : "l"(p));
    return a;
}
__device__ __forceinline__ uint32_t swz(uint32_t b) { return b ^ ((b >> 3) & 0x70); }

__device__ __forceinline__ void cp16(uint32_t s, const void* g) {
    asm volatile("cp.async.cg.shared.global [%0], [%1], 16;" :: "r"(s), "l"(g));
}
__device__ __forceinline__ void ldsm4(uint32_t& r0, uint32_t& r1, uint32_t& r2, uint32_t& r3,
                                      uint32_t a) {
    asm volatile("ldmatrix.sync.aligned.m8n8.x4.shared.b16 {%0,%1,%2,%3}, [%4];"
                 : "=r"(r0), "=r"(r1), "=r"(r2), "=r"(r3) : "r"(a));
}
__device__ __forceinline__ void mma16816(float* c, const uint32_t* a, const uint32_t* b) {
    asm volatile("mma.sync.aligned.m16n8k16.row.col.f32.bf16.bf16.f32 "
                 "{%0,%1,%2,%3}, {%4,%5,%6,%7}, {%8,%9}, {%0,%1,%2,%3};"
                 : "+f"(c[0]), "+f"(c[1]), "+f"(c[2]), "+f"(c[3])
                 : "r"(a[0]), "r"(a[1]), "r"(a[2]), "r"(a[3]), "r"(b[0]), "r"(b[1]));
}

// ---------------- init (comp labels + lane caches) ----------------
__global__ void init_kernel() {
    int i = blockIdx.x * 256 + threadIdx.x;       // 0..262143
    int mat = i >> 17;                            // 131072 entries per matrix
    int rl  = i & 131071;
    g_lanebest[mat][rl >> 5][rl & 31] = 0ull;     // 0 = "must scan" sentinel
    if (rl < NPTS) {
        g_comp[mat][rl] = rl;
        g_rowbest[mat][rl] = INFKEY;
        if (rl == 0) { g_ndeaths[mat] = 0; g_done[mat] = 0; }
    }
}

// ---------------- prep: hi/lo packed operands + sq norms + L2-diff (warp/row) ----------------
__global__ void prep_kernel(const float* __restrict__ x1, const float* __restrict__ x2) {
    int w    = (blockIdx.x * 256 + threadIdx.x) >> 5;   // 0..8191
    int lane = threadIdx.x & 31;
    int mat  = w >> 12;
    int row  = w & (NPTS - 1);
    const float* p = (mat ? x2 : x1) + (size_t)row * DIM;
    const float* q = x2 + (size_t)row * DIM;
    __nv_bfloat16* pa = g_pkA[mat] + (size_t)row * KPK;
    __nv_bfloat16* pb = g_pkB[mat] + (size_t)row * KPK;
    float s = 0.f, sd = 0.f;
    for (int c = lane * 4; c < DIM; c += 128) {
        float4 v = *(const float4*)(p + c);
        __nv_bfloat16 h0 = __float2bfloat16(v.x), h1 = __float2bfloat16(v.y);
        __nv_bfloat16 h2 = __float2bfloat16(v.z), h3 = __float2bfloat16(v.w);
        __nv_bfloat16 l0 = __float2bfloat16(v.x - __bfloat162float(h0));
        __nv_bfloat16 l1 = __float2bfloat16(v.y - __bfloat162float(h1));
        __nv_bfloat16 l2 = __float2bfloat16(v.z - __bfloat162float(h2));
        __nv_bfloat16 l3 = __float2bfloat16(v.w - __bfloat162float(h3));
        ushort4 hs = make_ushort4(__bfloat16_as_ushort(h0), __bfloat16_as_ushort(h1),
                                  __bfloat16_as_ushort(h2), __bfloat16_as_ushort(h3));
        ushort4 ls = make_ushort4(__bfloat16_as_ushort(l0), __bfloat16_as_ushort(l1),
                                  __bfloat16_as_ushort(l2), __bfloat16_as_ushort(l3));
        *(ushort4*)(pa + c)        = hs;   // A: [hi | lo | hi]
        *(ushort4*)(pa + 512 + c)  = ls;
        *(ushort4*)(pa + 1024 + c) = hs;
        *(ushort4*)(pb + c)        = hs;   // B: [hi | hi | lo]
        *(ushort4*)(pb + 512 + c)  = hs;
        *(ushort4*)(pb + 1024 + c) = ls;
        s += v.x * v.x + v.y * v.y + v.z * v.z + v.w * v.w;
        if (mat == 0) {
            float4 u = *(const float4*)(q + c);
            float d0 = v.x - u.x, d1 = v.y - u.y, d2 = v.z - u.z, d3 = v.w - u.w;
            sd += d0 * d0 + d1 * d1 + d2 * d2 + d3 * d3;
        }
    }
    #pragma unroll
    for (int o = 16; o > 0; o >>= 1) {
        s  += __shfl_xor_sync(0xffffffffu, s, o);
        sd += __shfl_xor_sync(0xffffffffu, sd, o);
    }
    if (lane == 0) {
        g_sq[mat][row] = s;
        if (mat == 0) g_rowdiff[row] = sd;
    }
}

// ---------------- distance matrix: mma.sync bf16 GEMM, M128 N128 K1536 ----------------
// 4 warps (2m x 2n), warp tile 64x64, BK=64 double-buffered via cp.async.
__global__ void __launch_bounds__(128, 2) dist_hmma_kernel() {
    extern __shared__ __align__(128) unsigned char sraw[];
    int mat = blockIdx.z;
    int t = blockIdx.x, bi = 0, len = 32;
    while (t >= len) { t -= len; len--; bi++; }
    int bj = bi + t;

    const __nv_bfloat16* pkA = g_pkA[mat];
    const __nv_bfloat16* pkB = g_pkB[mat];
    float* Dst = g_dist[mat];
    int tid = threadIdx.x, lane = tid & 31, wid = tid >> 5;
    int wm = wid & 1, wn = wid >> 1;           // warp tile: rows wm*64, cols wn*64
    uint32_t sb = smem_u32(sraw);

    float acc[4][8][4];
    #pragma unroll
    for (int im = 0; im < 4; im++)
        #pragma unroll
        for (int in = 0; in < 8; in++)
            #pragma unroll
            for (int q = 0; q < 4; q++) acc[im][in][q] = 0.f;

    int rowA0 = bi * 128, rowB0 = bj * 128;
    // per stage: A 128 rows x 128B (16KB) + B same; buffers A:[0,32K) B:[32K,64K)
    #define ISSUE(s) do {                                                           \
        int _b = (s) & 1; int _k0 = (s) * BK;                                       \
        _Pragma("unroll")                                                           \
        for (int _h = 0; _h < 8; _h++) {                                            \
            int _tt = tid + _h * 128;                                               \
            int _row = _tt >> 3, _c16 = _tt & 7;                                    \
            uint32_t _so = swz((uint32_t)(_row * 128 + _c16 * 16));                 \
            cp16(sb + _b * 16384 + _so,                                             \
                 pkA + (size_t)(rowA0 + _row) * KPK + _k0 + _c16 * 8);              \
            cp16(sb + 32768 + _b * 16384 + _so,                                     \
                 pkB + (size_t)(rowB0 + _row) * KPK + _k0 + _c16 * 8);              \
        }                                                                           \
        asm volatile("cp.async.commit_group;" ::: "memory");                        \
    } while (0)

    ISSUE(0);
    for (int s = 0; s < NSTAGE; s++) {
        if (s < NSTAGE - 1) { ISSUE(s + 1); asm volatile("cp.async.wait_group 1;" ::: "memory"); }
        else                {               asm volatile("cp.async.wait_group 0;" ::: "memory"); }
        __syncthreads();
        uint32_t baseA = sb + (s & 1) * 16384;
        uint32_t baseB = sb + 32768 + (s & 1) * 16384;
        #pragma unroll
        for (int kk = 0; kk < 4; kk++) {
            uint32_t a[4][4], bb[8][2];
            #pragma unroll
            for (int im = 0; im < 4; im++) {
                uint32_t addr = baseA + swz((uint32_t)((wm * 64 + im * 16 + (lane & 15)) * 128
                                                       + kk * 32 + (lane >> 4) * 16));
                ldsm4(a[im][0], a[im][1], a[im][2], a[im][3], addr);
            }
            #pragma unroll
            for (int np = 0; np < 4; np++) {
                uint32_t addr = baseB + swz((uint32_t)((wn * 64 + np * 16 + ((lane >> 4) << 3)
                                                        + (lane & 7)) * 128
                                                       + kk * 32 + ((lane >> 3) & 1) * 16));
                uint32_t r0, r1, r2, r3;
                ldsm4(r0, r1, r2, r3, addr);
                bb[np * 2][0] = r0; bb[np * 2][1] = r1;
                bb[np * 2 + 1][0] = r2; bb[np * 2 + 1][1] = r3;
            }
            #pragma unroll
            for (int im = 0; im < 4; im++)
                #pragma unroll
                for (int in = 0; in < 8; in++)
                    mma16816(acc[im][in], a[im], bb[in]);
        }
        __syncthreads();
    }
    #undef ISSUE

    // ---- epilogue: dist transform + row-major stores ----
    bool diag = (bi == bj);
    int giBase = bi * 128, gjBase = bj * 128;
    float sqr[4][2], sqc[8][2];
    #pragma unroll
    for (int im = 0; im < 4; im++)
        #pragma unroll
        for (int p = 0; p < 2; p++)
            sqr[im][p] = g_sq[mat][giBase + wm * 64 + im * 16 + (lane >> 2) + p * 8];
    #pragma unroll
    for (int in = 0; in < 8; in++) {
        int col = gjBase + wn * 64 + in * 8 + (lane & 3) * 2;
        sqc[in][0] = g_sq[mat][col];
        sqc[in][1] = g_sq[mat][col + 1];
    }
    #pragma unroll
    for (int im = 0; im < 4; im++) {
        #pragma unroll
        for (int in = 0; in < 8; in++) {
            #pragma unroll
            for (int p = 0; p < 2; p++) {
                int m = giBase + wm * 64 + im * 16 + (lane >> 2) + p * 8;
                int n = gjBase + wn * 64 + in * 8 + (lane & 3) * 2;
                float d0 = sqr[im][p] + sqc[in][0] - 2.f * acc[im][in][p * 2];
                float d1 = sqr[im][p] + sqc[in][1] - 2.f * acc[im][in][p * 2 + 1];
                d0 = sqrtf(fmaxf(d0, 1e-12f));
                d1 = sqrtf(fmaxf(d1, 1e-12f));
                if (diag) { if (m == n) d0 = BIGF; if (m == n + 1) d1 = BIGF; }
                acc[im][in][p * 2]     = d0;
                acc[im][in][p * 2 + 1] = d1;
                *(float2*)(Dst + (size_t)m * NPTS + n) = make_float2(d0, d1);
            }
        }
    }

    // ---- mirror via smem transpose (two 64-col chunks) ----
    if (!diag) {
        float* trans = (float*)sraw;
        #pragma unroll
        for (int h = 0; h < 2; h++) {
            __syncthreads();
            if (wn == h) {
                #pragma unroll
                for (int im = 0; im < 4; im++)
                    #pragma unroll
                    for (int in = 0; in < 8; in++)
                        #pragma unroll
                        for (int p = 0; p < 2; p++) {
                            int ml = wm * 64 + im * 16 + (lane >> 2) + p * 8;
                            int nl = in * 8 + (lane & 3) * 2;
                            trans[nl * TRANS_LD + ml]       = acc[im][in][p * 2];
                            trans[(nl + 1) * TRANS_LD + ml] = acc[im][in][p * 2 + 1];
                        }
            }
            __syncthreads();
            int r = tid >> 1, seg = tid & 1;
            const float* srcp = trans + r * TRANS_LD + seg * 64;
            float* dstp = Dst + (size_t)(gjBase + h * 64 + r) * NPTS + giBase + seg * 64;
            #pragma unroll
            for (int i = 0; i < 16; i++)
                *(float4*)(dstp + i * 4) = *(const float4*)(srcp + i * 4);
        }
    }
}

// ---------------- Boruvka scan: warp/row, per-lane exact cache ----------------
__global__ void __launch_bounds__(256) boruvka_scan() {
    int w    = (blockIdx.x * 256 + threadIdx.x) >> 5;   // 0..8191
    int lane = threadIdx.x & 31;
    int mat  = w >> 12;
    int row  = w & (NPTS - 1);
    if (g_done[mat]) return;

    int myc = g_comp[mat][row];
    unsigned long long lk = g_lanebest[mat][row][lane];

    // validity: sentinel 0 => scan; INF => no outgoing in slice (stays true);
    // else valid iff cached endpoint still outside my component (comps only grow)
    bool need = (lk == 0ull);
    if (!need && lk != INFKEY) {
        int eid = (int)(lk & 0xFFFFFF);
        int u = eid >> 12, v = eid & (NPTS - 1);
        int other = (u == row) ? v : u;
        need = (g_comp[mat][other] == myc);
    }
    if (need) {
        const float4* drow = (const float4*)(g_dist[mat] + (size_t)row * NPTS);
        const int4*   crow = (const int4*)(g_comp[mat]);
        unsigned long long best = INFKEY;
        for (int t = lane; t < NPTS / 4; t += 32) {
            float4 d = drow[t];
            int4   c = crow[t];
            int k = t * 4;
            if (c.x != myc) {
                int lo = min(row, k),     hi = max(row, k);
                best = min(best, ((unsigned long long)__float_as_uint(d.x) << 24)
                                 | (unsigned long long)((lo << 12) | hi));
            }
            if (c.y != myc) {
                int lo = min(row, k + 1), hi = max(row, k + 1);
                best = min(best, ((unsigned long long)__float_as_uint(d.y) << 24)
                                 | (unsigned long long)((lo << 12) | hi));
            }
            if (c.z != myc) {
                int lo = min(row, k + 2), hi = max(row, k + 2);
                best = min(best, ((unsigned long long)__float_as_uint(d.z) << 24)
                                 | (unsigned long long)((lo << 12) | hi));
            }
            if (c.w != myc) {
                int lo = min(row, k + 3), hi = max(row, k + 3);
                best = min(best, ((unsigned long long)__float_as_uint(d.w) << 24)
                                 | (unsigned long long)((lo << 12) | hi));
            }
        }
        lk = best;
        g_lanebest[mat][row][lane] = lk;
    }
    __syncwarp(0xffffffffu);
    unsigned long long rb = lk;
    #pragma unroll
    for (int o = 16; o > 0; o >>= 1) {
        unsigned long long other = __shfl_xor_sync(0xffffffffu, rb, o);
        rb = min(rb, other);
    }
    if (lane == 0) g_rowbest[mat][row] = rb;
}

// ---------------- Boruvka merge: one block per matrix ----------------
__global__ void __launch_bounds__(1024) boruvka_merge() {
    int mat = blockIdx.x;
    if (g_done[mat]) return;

    __shared__ unsigned long long sbest[NPTS];   // 32KB
    __shared__ unsigned short    par[NPTS];      // 8KB
    __shared__ int s_roots;

    int tid = threadIdx.x;
    for (int c = tid; c < NPTS; c += 1024) sbest[c] = INFKEY;
    __syncthreads();

    for (int r = tid; r < NPTS; r += 1024) {
        unsigned long long k = g_rowbest[mat][r];
        if (k != INFKEY) atomicMin(&sbest[g_comp[mat][r]], k);
    }
    __syncthreads();

    for (int c = tid; c < NPTS; c += 1024) {
        unsigned long long k = sbest[c];
        int p = c;
        if (k != INFKEY) {
            int eid = (int)(k & 0xFFFFFF);
            int u = eid >> 12, v = eid & (NPTS - 1);
            int cu = g_comp[mat][u];
            int d = (cu == c) ? g_comp[mat][v] : cu;
            p = d;
            bool mutual = (sbest[d] == k);
            if (!(mutual && c > d)) {
                float wgt = __uint_as_float((unsigned)(k >> 24));
                int pos = atomicAdd(&g_ndeaths[mat], 1);
                g_deaths[mat][pos] = wgt;
            }
        }
        par[c] = (unsigned short)p;
    }
    __syncthreads();

    for (int c = tid; c < NPTS; c += 1024) {
        int p = par[c];
        if (p != c && par[p] == c && c < p) par[c] = (unsigned short)c;
    }
    __syncthreads();

    for (int it = 0; it < 12; it++) {
        for (int c = tid; c < NPTS; c += 1024) par[c] = par[par[c]];
        __syncthreads();
    }

    if (tid == 0) s_roots = 0;
    __syncthreads();
    for (int i = tid; i < NPTS; i += 1024) {
        int nc = par[g_comp[mat][i]];
        g_comp[mat][i] = nc;
        if (nc == i) atomicAdd(&s_roots, 1);
    }
    __syncthreads();
    if (tid == 0 && s_roots <= 1) g_done[mat] = 1;
}

// ---------------- bitonic sort of deaths (pad slot 4095 with 0) ----------------
__global__ void __launch_bounds__(1024) sort_kernel() {
    int mat = blockIdx.x;
    __shared__ float s[NPTS];
    for (int i = threadIdx.x; i < NPTS; i += 1024)
        s[i] = (i < NPTS - 1) ? g_deaths[mat][i] : 0.0f;
    __syncthreads();
    for (int k = 2; k <= NPTS; k <<= 1)
        for (int j2 = k >> 1; j2 > 0; j2 >>= 1) {
            for (int i = threadIdx.x; i < NPTS; i += 1024) {
                int ixj = i ^ j2;
                if (ixj > i) {
                    float a = s[i], b = s[ixj];
                    bool up = ((i & k) == 0);
                    if ((a > b) == up) { s[i] = b; s[ixj] = a; }
                }
            }
            __syncthreads();
        }
    for (int i = threadIdx.x; i < NPTS; i += 1024)
        g_deaths[mat][i] = s[i];
}

// ---------------- final: Wasserstein-1 match + L2 loss, deterministic ----------------
__global__ void __launch_bounds__(1024) final_kernel(float* __restrict__ out) {
    __shared__ float red[1024];
    int tid = threadIdx.x;
    const float inv = 1.0f / ((float)NPTS * (float)DIM);
    float s = 0.f;
    for (int i = tid; i < NPTS; i += 1024) {
        float a = g_deaths[0][i], b = g_deaths[1][i];
        s += fminf(fabsf(a - b), 0.5f * (a + b));
        s += g_rowdiff[i] * inv;
    }
    red[tid] = s; __syncthreads();
    #pragma unroll
    for (int st = 512; st > 0; st >>= 1) {
        if (tid < st) red[tid] += red[tid + st];
        __syncthreads();
    }
    if (tid == 0) out[0] = red[0];
}

extern "C" void kernel_launch(void* const* d_in, const int* in_sizes, int n_in,
                              void* d_out, int out_size) {
    const float* x1 = (const float*)d_in[0];
    const float* x2 = (const float*)d_in[1];
    float* out = (float*)d_out;

    cudaFuncSetAttribute(dist_hmma_kernel, cudaFuncAttributeMaxDynamicSharedMemorySize, 65536);

    init_kernel<<<1024, 256>>>();
    prep_kernel<<<1024, 256>>>(x1, x2);
    dist_hmma_kernel<<<dim3(528, 1, 2), 128, 65536>>>();
    for (int r = 0; r < 12; r++) {
        boruvka_scan <<<1024, 256>>>();
        boruvka_merge<<<2, 1024>>>();
    }
    sort_kernel<<<2, 1024>>>();
    final_kernel<<<1, 1024>>>(out);
}

// round 8
// speedup vs baseline: 12.5520x; 1.0511x over previous
#include <cuda_runtime.h>
#include <cuda_bf16.h>
#include <math.h>
#include <stdint.h>

#define NPTS 4096
#define DIM  512
#define KPK  1536              // packed K = [512 | 512 | 512]
#define BK   64
#define NSTAGE (KPK / BK)      // 24
#define BIGF   1e30f
#define INFKEY 0xFFFFFFFFFFFFFFFFull
#define TRANS_LD 132

// ---------------- scratch (static device globals; no allocation) ----------------
__device__ float g_dist[2][(size_t)NPTS * NPTS];            // 2 x 64MB distance matrices
__device__ __nv_bfloat16 g_pkA[2][(size_t)NPTS * KPK];      // [hi | lo | hi]
__device__ __nv_bfloat16 g_pkB[2][(size_t)NPTS * KPK];      // [hi | hi | lo]
__device__ float g_sq[2][NPTS];                             // squared norms (fp32)
__device__ float g_rowdiff[NPTS];                           // per-row (x1-x2)^2 sums
__device__ float g_deaths[2][NPTS];                         // MST edge weights (4095 used)
__device__ int   g_comp[2][NPTS];                           // Boruvka component labels
__device__ unsigned long long g_lanebest[2][NPTS][32];      // per-lane cached min outgoing
__device__ unsigned long long g_rowbest[2][NPTS];           // per-row best outgoing edge key
__device__ int   g_ndeaths[2];
__device__ int   g_done[2];

// ---------------- helpers ----------------
__device__ __forceinline__ uint32_t smem_u32(const void* p) {
    uint32_t a;
    asm("{ .reg .u64 t; cvta.to.shared.u64 t, %1; cvt.u32.u64 %0, t; }" : "=r"(a) : "l"(p));
    return a;
}
__device__ __forceinline__ uint32_t swz(uint32_t b) { return b ^ ((b >> 3) & 0x70); }

__device__ __forceinline__ void cp16(uint32_t s, const void* g) {
    asm volatile("cp.async.cg.shared.global [%0], [%1], 16;" :: "r"(s), "l"(g));
}
__device__ __forceinline__ void ldsm4(uint32_t& r0, uint32_t& r1, uint32_t& r2, uint32_t& r3,
                                      uint32_t a) {
    asm volatile("ldmatrix.sync.aligned.m8n8.x4.shared.b16 {%0,%1,%2,%3}, [%4];"
                 : "=r"(r0), "=r"(r1), "=r"(r2), "=r"(r3) : "r"(a));
}
__device__ __forceinline__ void mma16816(float* c, const uint32_t* a, const uint32_t* b) {
    asm volatile("mma.sync.aligned.m16n8k16.row.col.f32.bf16.bf16.f32 "
                 "{%0,%1,%2,%3}, {%4,%5,%6,%7}, {%8,%9}, {%0,%1,%2,%3};"
                 : "+f"(c[0]), "+f"(c[1]), "+f"(c[2]), "+f"(c[3])
                 : "r"(a[0]), "r"(a[1]), "r"(a[2]), "r"(a[3]), "r"(b[0]), "r"(b[1]));
}

// ---------------- init (comp labels + lane caches) ----------------
__global__ void init_kernel() {
    int i = blockIdx.x * 256 + threadIdx.x;       // 0..262143
    int mat = i >> 17;                            // 131072 entries per matrix
    int rl  = i & 131071;
    g_lanebest[mat][rl >> 5][rl & 31] = 0ull;     // 0 = "must scan" sentinel
    if (rl < NPTS) {
        g_comp[mat][rl] = rl;
        g_rowbest[mat][rl] = INFKEY;
        if (rl == 0) { g_ndeaths[mat] = 0; g_done[mat] = 0; }
    }
}

// ---------------- prep: hi/lo packed operands + sq norms + L2-diff (warp/row) ----------------
__global__ void prep_kernel(const float* __restrict__ x1, const float* __restrict__ x2) {
    int w    = (blockIdx.x * 256 + threadIdx.x) >> 5;   // 0..8191
    int lane = threadIdx.x & 31;
    int mat  = w >> 12;
    int row  = w & (NPTS - 1);
    const float* p = (mat ? x2 : x1) + (size_t)row * DIM;
    const float* q = x2 + (size_t)row * DIM;
    __nv_bfloat16* pa = g_pkA[mat] + (size_t)row * KPK;
    __nv_bfloat16* pb = g_pkB[mat] + (size_t)row * KPK;
    float s = 0.f, sd = 0.f;
    for (int c = lane * 4; c < DIM; c += 128) {
        float4 v = *(const float4*)(p + c);
        __nv_bfloat16 h0 = __float2bfloat16(v.x), h1 = __float2bfloat16(v.y);
        __nv_bfloat16 h2 = __float2bfloat16(v.z), h3 = __float2bfloat16(v.w);
        __nv_bfloat16 l0 = __float2bfloat16(v.x - __bfloat162float(h0));
        __nv_bfloat16 l1 = __float2bfloat16(v.y - __bfloat162float(h1));
        __nv_bfloat16 l2 = __float2bfloat16(v.z - __bfloat162float(h2));
        __nv_bfloat16 l3 = __float2bfloat16(v.w - __bfloat162float(h3));
        ushort4 hs = make_ushort4(__bfloat16_as_ushort(h0), __bfloat16_as_ushort(h1),
                                  __bfloat16_as_ushort(h2), __bfloat16_as_ushort(h3));
        ushort4 ls = make_ushort4(__bfloat16_as_ushort(l0), __bfloat16_as_ushort(l1),
                                  __bfloat16_as_ushort(l2), __bfloat16_as_ushort(l3));
        *(ushort4*)(pa + c)        = hs;   // A: [hi | lo | hi]
        *(ushort4*)(pa + 512 + c)  = ls;
        *(ushort4*)(pa + 1024 + c) = hs;
        *(ushort4*)(pb + c)        = hs;   // B: [hi | hi | lo]
        *(ushort4*)(pb + 512 + c)  = hs;
        *(ushort4*)(pb + 1024 + c) = ls;
        s += v.x * v.x + v.y * v.y + v.z * v.z + v.w * v.w;
        if (mat == 0) {
            float4 u = *(const float4*)(q + c);
            float d0 = v.x - u.x, d1 = v.y - u.y, d2 = v.z - u.z, d3 = v.w - u.w;
            sd += d0 * d0 + d1 * d1 + d2 * d2 + d3 * d3;
        }
    }
    #pragma unroll
    for (int o = 16; o > 0; o >>= 1) {
        s  += __shfl_xor_sync(0xffffffffu, s, o);
        sd += __shfl_xor_sync(0xffffffffu, sd, o);
    }
    if (lane == 0) {
        g_sq[mat][row] = s;
        if (mat == 0) g_rowdiff[row] = sd;
    }
}

// ---------------- distance matrix: mma.sync bf16 GEMM, M128 N128 K1536 ----------------
// 8 warps (4m x 2n), warp tile 32x64, BK=64 (128B rows, conflict-free ldmatrix).
__global__ void __launch_bounds__(256, 2) dist_hmma_kernel() {
    extern __shared__ __align__(128) unsigned char sraw[];
    int mat = blockIdx.z;
    int t = blockIdx.x, bi = 0, len = 32;
    while (t >= len) { t -= len; len--; bi++; }
    int bj = bi + t;

    const __nv_bfloat16* pkA = g_pkA[mat];
    const __nv_bfloat16* pkB = g_pkB[mat];
    float* Dst = g_dist[mat];
    int tid = threadIdx.x, lane = tid & 31, wid = tid >> 5;
    int wm = wid & 3, wn = wid >> 2;           // warp tile: rows wm*32, cols wn*64
    uint32_t sb = smem_u32(sraw);

    float acc[2][8][4];
    #pragma unroll
    for (int im = 0; im < 2; im++)
        #pragma unroll
        for (int in = 0; in < 8; in++)
            #pragma unroll
            for (int q = 0; q < 4; q++) acc[im][in][q] = 0.f;

    int rowA0 = bi * 128, rowB0 = bj * 128;
    // per stage: A 128 rows x 128B (16KB) + B same; A buffers [0,32K), B [32K,64K)
    #define ISSUE(s) do {                                                           \
        int _b = (s) & 1; int _k0 = (s) * BK;                                       \
        _Pragma("unroll")                                                           \
        for (int _h = 0; _h < 4; _h++) {                                            \
            int _tt = tid + _h * 256;                                               \
            int _row = _tt >> 3, _c16 = _tt & 7;                                    \
            uint32_t _so = swz((uint32_t)(_row * 128 + _c16 * 16));                 \
            cp16(sb + _b * 16384 + _so,                                             \
                 pkA + (size_t)(rowA0 + _row) * KPK + _k0 + _c16 * 8);              \
            cp16(sb + 32768 + _b * 16384 + _so,                                     \
                 pkB + (size_t)(rowB0 + _row) * KPK + _k0 + _c16 * 8);              \
        }                                                                           \
        asm volatile("cp.async.commit_group;" ::: "memory");                        \
    } while (0)

    ISSUE(0);
    for (int s = 0; s < NSTAGE; s++) {
        if (s < NSTAGE - 1) { ISSUE(s + 1); asm volatile("cp.async.wait_group 1;" ::: "memory"); }
        else                {               asm volatile("cp.async.wait_group 0;" ::: "memory"); }
        __syncthreads();
        uint32_t baseA = sb + (s & 1) * 16384;
        uint32_t baseB = sb + 32768 + (s & 1) * 16384;
        #pragma unroll
        for (int kk = 0; kk < 4; kk++) {
            uint32_t a[2][4], bb[8][2];
            #pragma unroll
            for (int im = 0; im < 2; im++) {
                uint32_t addr = baseA + swz((uint32_t)((wm * 32 + im * 16 + (lane & 15)) * 128
                                                       + kk * 32 + (lane >> 4) * 16));
                ldsm4(a[im][0], a[im][1], a[im][2], a[im][3], addr);
            }
            #pragma unroll
            for (int np = 0; np < 4; np++) {
                uint32_t addr = baseB + swz((uint32_t)((wn * 64 + np * 16 + ((lane >> 4) << 3)
                                                        + (lane & 7)) * 128
                                                       + kk * 32 + ((lane >> 3) & 1) * 16));
                uint32_t r0, r1, r2, r3;
                ldsm4(r0, r1, r2, r3, addr);
                bb[np * 2][0] = r0; bb[np * 2][1] = r1;
                bb[np * 2 + 1][0] = r2; bb[np * 2 + 1][1] = r3;
            }
            #pragma unroll
            for (int im = 0; im < 2; im++)
                #pragma unroll
                for (int in = 0; in < 8; in++)
                    mma16816(acc[im][in], a[im], bb[in]);
        }
        __syncthreads();
    }
    #undef ISSUE

    // ---- epilogue: dist transform + row-major stores ----
    bool diag = (bi == bj);
    int giBase = bi * 128, gjBase = bj * 128;
    float sqr[2][2], sqc[8][2];
    #pragma unroll
    for (int im = 0; im < 2; im++)
        #pragma unroll
        for (int p = 0; p < 2; p++)
            sqr[im][p] = g_sq[mat][giBase + wm * 32 + im * 16 + (lane >> 2) + p * 8];
    #pragma unroll
    for (int in = 0; in < 8; in++) {
        int col = gjBase + wn * 64 + in * 8 + (lane & 3) * 2;
        sqc[in][0] = g_sq[mat][col];
        sqc[in][1] = g_sq[mat][col + 1];
    }
    #pragma unroll
    for (int im = 0; im < 2; im++) {
        #pragma unroll
        for (int in = 0; in < 8; in++) {
            #pragma unroll
            for (int p = 0; p < 2; p++) {
                int m = giBase + wm * 32 + im * 16 + (lane >> 2) + p * 8;
                int n = gjBase + wn * 64 + in * 8 + (lane & 3) * 2;
                float d0 = sqr[im][p] + sqc[in][0] - 2.f * acc[im][in][p * 2];
                float d1 = sqr[im][p] + sqc[in][1] - 2.f * acc[im][in][p * 2 + 1];
                d0 = sqrtf(fmaxf(d0, 1e-12f));
                d1 = sqrtf(fmaxf(d1, 1e-12f));
                if (diag) { if (m == n) d0 = BIGF; if (m == n + 1) d1 = BIGF; }
                acc[im][in][p * 2]     = d0;
                acc[im][in][p * 2 + 1] = d1;
                *(float2*)(Dst + (size_t)m * NPTS + n) = make_float2(d0, d1);
            }
        }
    }

    // ---- mirror via smem transpose (two 64-col chunks; 256 threads -> 64 rows x 4 segs) ----
    if (!diag) {
        float* trans = (float*)sraw;
        #pragma unroll
        for (int h = 0; h < 2; h++) {
            __syncthreads();
            if (wn == h) {
                #pragma unroll
                for (int im = 0; im < 2; im++)
                    #pragma unroll
                    for (int in = 0; in < 8; in++)
                        #pragma unroll
                        for (int p = 0; p < 2; p++) {
                            int ml = wm * 32 + im * 16 + (lane >> 2) + p * 8;
                            int nl = in * 8 + (lane & 3) * 2;
                            trans[nl * TRANS_LD + ml]       = acc[im][in][p * 2];
                            trans[(nl + 1) * TRANS_LD + ml] = acc[im][in][p * 2 + 1];
                        }
            }
            __syncthreads();
            int r = tid >> 2, seg = tid & 3;       // 64 rows x 4 segments of 32 floats
            const float* srcp = trans + r * TRANS_LD + seg * 32;
            float* dstp = Dst + (size_t)(gjBase + h * 64 + r) * NPTS + giBase + seg * 32;
            #pragma unroll
            for (int i = 0; i < 8; i++)
                *(float4*)(dstp + i * 4) = *(const float4*)(srcp + i * 4);
        }
    }
}

// ---------------- Boruvka scan: warp/row, per-lane exact cache ----------------
__global__ void __launch_bounds__(256) boruvka_scan() {
    int w    = (blockIdx.x * 256 + threadIdx.x) >> 5;   // 0..8191
    int lane = threadIdx.x & 31;
    int mat  = w >> 12;
    int row  = w & (NPTS - 1);
    if (g_done[mat]) return;

    int myc = g_comp[mat][row];
    unsigned long long lk = g_lanebest[mat][row][lane];

    bool need = (lk == 0ull);
    if (!need && lk != INFKEY) {
        int eid = (int)(lk & 0xFFFFFF);
        int u = eid >> 12, v = eid & (NPTS - 1);
        int other = (u == row) ? v : u;
        need = (g_comp[mat][other] == myc);
    }
    if (need) {
        const float4* drow = (const float4*)(g_dist[mat] + (size_t)row * NPTS);
        const int4*   crow = (const int4*)(g_comp[mat]);
        unsigned long long best = INFKEY;
        for (int t = lane; t < NPTS / 4; t += 32) {
            float4 d = drow[t];
            int4   c = crow[t];
            int k = t * 4;
            if (c.x != myc) {
                int lo = min(row, k),     hi = max(row, k);
                best = min(best, ((unsigned long long)__float_as_uint(d.x) << 24)
                                 | (unsigned long long)((lo << 12) | hi));
            }
            if (c.y != myc) {
                int lo = min(row, k + 1), hi = max(row, k + 1);
                best = min(best, ((unsigned long long)__float_as_uint(d.y) << 24)
                                 | (unsigned long long)((lo << 12) | hi));
            }
            if (c.z != myc) {
                int lo = min(row, k + 2), hi = max(row, k + 2);
                best = min(best, ((unsigned long long)__float_as_uint(d.z) << 24)
                                 | (unsigned long long)((lo << 12) | hi));
            }
            if (c.w != myc) {
                int lo = min(row, k + 3), hi = max(row, k + 3);
                best = min(best, ((unsigned long long)__float_as_uint(d.w) << 24)
                                 | (unsigned long long)((lo << 12) | hi));
            }
        }
        lk = best;
        g_lanebest[mat][row][lane] = lk;
    }
    __syncwarp(0xffffffffu);
    unsigned long long rb = lk;
    #pragma unroll
    for (int o = 16; o > 0; o >>= 1) {
        unsigned long long other = __shfl_xor_sync(0xffffffffu, rb, o);
        rb = min(rb, other);
    }
    if (lane == 0) g_rowbest[mat][row] = rb;
}

// ---------------- Boruvka merge: one block per matrix (early-exit jumping) ----------------
__global__ void __launch_bounds__(1024) boruvka_merge() {
    int mat = blockIdx.x;
    if (g_done[mat]) return;

    __shared__ unsigned long long sbest[NPTS];   // 32KB
    __shared__ unsigned short    par[NPTS];      // 8KB
    __shared__ int s_roots;

    int tid = threadIdx.x;
    for (int c = tid; c < NPTS; c += 1024) sbest[c] = INFKEY;
    __syncthreads();

    for (int r = tid; r < NPTS; r += 1024) {
        unsigned long long k = g_rowbest[mat][r];
        if (k != INFKEY) atomicMin(&sbest[g_comp[mat][r]], k);
    }
    __syncthreads();

    for (int c = tid; c < NPTS; c += 1024) {
        unsigned long long k = sbest[c];
        int p = c;
        if (k != INFKEY) {
            int eid = (int)(k & 0xFFFFFF);
            int u = eid >> 12, v = eid & (NPTS - 1);
            int cu = g_comp[mat][u];
            int d = (cu == c) ? g_comp[mat][v] : cu;
            p = d;
            bool mutual = (sbest[d] == k);
            if (!(mutual && c > d)) {
                float wgt = __uint_as_float((unsigned)(k >> 24));
                int pos = atomicAdd(&g_ndeaths[mat], 1);
                g_deaths[mat][pos] = wgt;
            }
        }
        par[c] = (unsigned short)p;
    }
    __syncthreads();

    for (int c = tid; c < NPTS; c += 1024) {
        int p = par[c];
        if (p != c && par[p] == c && c < p) par[c] = (unsigned short)c;
    }
    __syncthreads();

    // pointer jumping with convergence early-exit (typical depth ~2-4)
    for (int it = 0; it < 12; it++) {
        int changed = 0;
        for (int c = tid; c < NPTS; c += 1024) {
            int p = par[c];
            int gp = par[p];
            if (gp != p) { par[c] = (unsigned short)gp; changed = 1; }
        }
        if (!__syncthreads_or(changed)) break;
    }

    if (tid == 0) s_roots = 0;
    __syncthreads();
    for (int i = tid; i < NPTS; i += 1024) {
        int nc = par[g_comp[mat][i]];
        g_comp[mat][i] = nc;
        if (nc == i) atomicAdd(&s_roots, 1);
    }
    __syncthreads();
    if (tid == 0 && s_roots <= 1) g_done[mat] = 1;
}

// ---------------- bitonic sort of deaths (pad slot 4095 with 0) ----------------
__global__ void __launch_bounds__(1024) sort_kernel() {
    int mat = blockIdx.x;
    __shared__ float s[NPTS];
    for (int i = threadIdx.x; i < NPTS; i += 1024)
        s[i] = (i < NPTS - 1) ? g_deaths[mat][i] : 0.0f;
    __syncthreads();
    for (int k = 2; k <= NPTS; k <<= 1)
        for (int j2 = k >> 1; j2 > 0; j2 >>= 1) {
            for (int i = threadIdx.x; i < NPTS; i += 1024) {
                int ixj = i ^ j2;
                if (ixj > i) {
                    float a = s[i], b = s[ixj];
                    bool up = ((i & k) == 0);
                    if ((a > b) == up) { s[i] = b; s[ixj] = a; }
                }
            }
            __syncthreads();
        }
    for (int i = threadIdx.x; i < NPTS; i += 1024)
        g_deaths[mat][i] = s[i];
}

// ---------------- final: Wasserstein-1 match + L2 loss, deterministic ----------------
__global__ void __launch_bounds__(1024) final_kernel(float* __restrict__ out) {
    __shared__ float red[1024];
    int tid = threadIdx.x;
    const float inv = 1.0f / ((float)NPTS * (float)DIM);
    float s = 0.f;
    for (int i = tid; i < NPTS; i += 1024) {
        float a = g_deaths[0][i], b = g_deaths[1][i];
        s += fminf(fabsf(a - b), 0.5f * (a + b));
        s += g_rowdiff[i] * inv;
    }
    red[tid] = s; __syncthreads();
    #pragma unroll
    for (int st = 512; st > 0; st >>= 1) {
        if (tid < st) red[tid] += red[tid + st];
        __syncthreads();
    }
    if (tid == 0) out[0] = red[0];
}

extern "C" void kernel_launch(void* const* d_in, const int* in_sizes, int n_in,
                              void* d_out, int out_size) {
    const float* x1 = (const float*)d_in[0];
    const float* x2 = (const float*)d_in[1];
    float* out = (float*)d_out;

    cudaFuncSetAttribute(dist_hmma_kernel, cudaFuncAttributeMaxDynamicSharedMemorySize, 65536);

    init_kernel<<<1024, 256>>>();
    prep_kernel<<<1024, 256>>>(x1, x2);
    dist_hmma_kernel<<<dim3(528, 1, 2), 256, 65536>>>();
    for (int r = 0; r < 12; r++) {
        boruvka_scan <<<1024, 256>>>();
        boruvka_merge<<<2, 1024>>>();
    }
    sort_kernel<<<2, 1024>>>();
    final_kernel<<<1, 1024>>>(out);
}